// round 4
// baseline (speedup 1.0000x reference)
#include <cuda_runtime.h>
#include <math.h>

#define BSZ   4
#define NPT   8192
#define CH    256
#define NPTS  (BSZ*NPT)      // 32768
#define QKVW  768
#define AP    8              // points per attention block

// -------------------- scratch (device globals; no cudaMalloc allowed) -----
__device__ float g_h[NPTS*CH];        // LN1 out, reused as LN2 out
__device__ float g_qkv[NPTS*QKVW];
__device__ float g_xattn[NPTS*CH];
__device__ float g_x[NPTS*CH];        // residual stream
__device__ float g_mlp1[NPTS*1024];

// -------------------- LayerNorm (one row per 256-thread block) ------------
__global__ void ln_kernel(const float* __restrict__ x, const float* __restrict__ g,
                          const float* __restrict__ b, float* __restrict__ out)
{
    int row = blockIdx.x;
    int c   = threadIdx.x;
    float v = x[row*CH + c];

    __shared__ float red[8];
    __shared__ float s_mean, s_rstd;

    float s = v;
    #pragma unroll
    for (int o = 16; o > 0; o >>= 1) s += __shfl_xor_sync(0xffffffffu, s, o);
    if ((c & 31) == 0) red[c >> 5] = s;
    __syncthreads();
    if (c == 0) {
        float t = 0.f;
        #pragma unroll
        for (int i = 0; i < 8; i++) t += red[i];
        s_mean = t * (1.0f / CH);
    }
    __syncthreads();
    float m = s_mean;
    float d = v - m;
    s = d * d;
    #pragma unroll
    for (int o = 16; o > 0; o >>= 1) s += __shfl_xor_sync(0xffffffffu, s, o);
    if ((c & 31) == 0) red[c >> 5] = s;
    __syncthreads();
    if (c == 0) {
        float t = 0.f;
        #pragma unroll
        for (int i = 0; i < 8; i++) t += red[i];
        s_rstd = rsqrtf(t * (1.0f / CH) + 1e-5f);
    }
    __syncthreads();
    out[row*CH + c] = d * s_rstd * g[c] + b[c];
}

// -------------------- SGEMM 128x128x8, 256 threads, 8x8 micro-tile --------
// EPI: 0 = none, 1 = +bias[col] +resid[row*N+col], 2 = gelu(acc + bias[col])
__device__ __forceinline__ float gelu_exact(float v) { return v * normcdff(v); }

template<int EPI>
__global__ void __launch_bounds__(256, 2)
sgemm(const float* __restrict__ A, const float* __restrict__ B,
      float* __restrict__ C, int M, int N, int K,
      const float* __restrict__ bias, const float* __restrict__ resid)
{
    const int BM = 128, BN = 128, BK = 8;
    __shared__ float As[BK][BM];
    __shared__ float Bs[BK][BN];

    int tid = threadIdx.x;
    int bm = blockIdx.y * BM;
    int bn = blockIdx.x * BN;
    int tx = tid & 15, ty = tid >> 4;

    int arow = tid >> 1, acol = (tid & 1) * 4;
    int brow = tid >> 5, bcol = (tid & 31) * 4;

    const float* Aptr = A + (size_t)(bm + arow) * K + acol;
    const float* Bptr = B + (size_t)brow * N + bn + bcol;

    float acc[8][8];
    #pragma unroll
    for (int i = 0; i < 8; i++)
        #pragma unroll
        for (int j = 0; j < 8; j++) acc[i][j] = 0.f;

    int nt = K / BK;

    // preload tile 0
    {
        float4 a4 = *(const float4*)Aptr;
        float4 b4 = *(const float4*)Bptr;
        As[acol+0][arow] = a4.x; As[acol+1][arow] = a4.y;
        As[acol+2][arow] = a4.z; As[acol+3][arow] = a4.w;
        *(float4*)&Bs[brow][bcol] = b4;
    }
    __syncthreads();

    for (int kt = 0; kt < nt; kt++) {
        float4 na, nb;
        if (kt + 1 < nt) {
            na = *(const float4*)(Aptr + (kt + 1) * BK);
            nb = *(const float4*)(Bptr + (size_t)(kt + 1) * BK * N);
        }
        #pragma unroll
        for (int k = 0; k < BK; k++) {
            float ar[8], br[8];
            *(float4*)(ar)     = *(const float4*)&As[k][ty*8];
            *(float4*)(ar + 4) = *(const float4*)&As[k][ty*8 + 4];
            *(float4*)(br)     = *(const float4*)&Bs[k][tx*8];
            *(float4*)(br + 4) = *(const float4*)&Bs[k][tx*8 + 4];
            #pragma unroll
            for (int i = 0; i < 8; i++)
                #pragma unroll
                for (int j = 0; j < 8; j++)
                    acc[i][j] = fmaf(ar[i], br[j], acc[i][j]);
        }
        __syncthreads();
        if (kt + 1 < nt) {
            As[acol+0][arow] = na.x; As[acol+1][arow] = na.y;
            As[acol+2][arow] = na.z; As[acol+3][arow] = na.w;
            *(float4*)&Bs[brow][bcol] = nb;
            __syncthreads();
        }
    }

    // epilogue
    #pragma unroll
    for (int i = 0; i < 8; i++) {
        int row = bm + ty*8 + i;
        #pragma unroll
        for (int jv = 0; jv < 2; jv++) {
            int col = bn + tx*8 + jv*4;
            float4 r;
            r.x = acc[i][jv*4+0]; r.y = acc[i][jv*4+1];
            r.z = acc[i][jv*4+2]; r.w = acc[i][jv*4+3];
            if (EPI >= 1) {
                float4 bv = *(const float4*)&bias[col];
                r.x += bv.x; r.y += bv.y; r.z += bv.z; r.w += bv.w;
            }
            if (EPI == 1) {
                float4 rv = *(const float4*)&resid[(size_t)row * N + col];
                r.x += rv.x; r.y += rv.y; r.z += rv.z; r.w += rv.w;
            }
            if (EPI == 2) {
                r.x = gelu_exact(r.x); r.y = gelu_exact(r.y);
                r.z = gelu_exact(r.z); r.w = gelu_exact(r.w);
            }
            *(float4*)&C[(size_t)row * N + col] = r;
        }
    }
}

// -------------------- KNN attention + fused pe projection -----------------
// Per point n:  attn[h,k] = softmax_k( q_h . k_h / 8 )
//   out = concat_h( sum_k attn*v_h )  +  (sum_k attn*t_k) @ w_d2[:,h-slice] + b_d2
// where t_k = relu(rel_k @ w_d1 + b_d1). The w_d2 projection is hoisted past
// the softmax sum (softmax sums to 1), turning 16 GEMVs into 1 per point.
__global__ void __launch_bounds__(256)
attn_kernel(const float* __restrict__ qkv, const int* __restrict__ nns,
            const float* __restrict__ xyz,
            const float* __restrict__ w_d1, const float* __restrict__ b_d1,
            const float* __restrict__ w_d2, const float* __restrict__ b_d2,
            float* __restrict__ xattn)
{
    __shared__ float sq[CH];
    __shared__ int   snbr[16];
    __shared__ float srelx[16], srely[16];
    __shared__ float spart[16][8];
    __shared__ float sattn[4][16];
    __shared__ float s_u[AP][4*CH];   // 32 KB
    __shared__ float s_av[AP][CH];    // 8 KB

    int c    = threadIdx.x;
    int h    = c >> 6;
    int lane = c & 31;
    int warp = c >> 5;

    float wd1x = w_d1[c];
    float wd1y = w_d1[CH + c];
    float bd1  = b_d1[c];

    int base = blockIdx.x * AP;

    for (int p = 0; p < AP; p++) {
        int pi = base + p;
        int bb = pi >> 13;                      // batch index (N = 8192)

        if (c < 16) {
            int j   = nns[pi*32 + c];           // first K=16 of NN=32
            int row = (bb << 13) + j;
            snbr[c]  = row;
            srelx[c] = xyz[pi*2]     - xyz[row*2];
            srely[c] = xyz[pi*2 + 1] - xyz[row*2 + 1];
        }
        sq[c] = qkv[(size_t)pi*QKVW + c];
        __syncthreads();

        // logits: 16 neighbors, per-head dot of 64 via warp reduce + pair add
        #pragma unroll
        for (int k = 0; k < 16; k++) {
            float pr = qkv[(size_t)snbr[k]*QKVW + CH + c] * sq[c];
            #pragma unroll
            for (int o = 16; o > 0; o >>= 1)
                pr += __shfl_xor_sync(0xffffffffu, pr, o);
            if (lane == 0) spart[k][warp] = pr;
        }
        __syncthreads();
        if (c < 64) {
            int k = c & 15, hh = c >> 4;
            sattn[hh][k] = (spart[k][2*hh] + spart[k][2*hh + 1]) * 0.125f;
        }
        __syncthreads();
        if (c < 4) {                            // softmax per head
            float mx = -1e30f;
            #pragma unroll
            for (int k = 0; k < 16; k++) mx = fmaxf(mx, sattn[c][k]);
            float sm = 0.f;
            #pragma unroll
            for (int k = 0; k < 16; k++) {
                float e = __expf(sattn[c][k] - mx);
                sattn[c][k] = e; sm += e;
            }
            float inv = 1.f / sm;
            #pragma unroll
            for (int k = 0; k < 16; k++) sattn[c][k] *= inv;
        }
        __syncthreads();

        // attn-weighted V, and u[h',c] = sum_k attn[h',k] * t[k,c]
        float av = 0.f, u0 = 0.f, u1 = 0.f, u2 = 0.f, u3 = 0.f;
        #pragma unroll
        for (int k = 0; k < 16; k++) {
            float v = qkv[(size_t)snbr[k]*QKVW + 2*CH + c];
            av = fmaf(sattn[h][k], v, av);
            float t = fmaxf(fmaf(srelx[k], wd1x, fmaf(srely[k], wd1y, bd1)), 0.f);
            u0 = fmaf(sattn[0][k], t, u0);
            u1 = fmaf(sattn[1][k], t, u1);
            u2 = fmaf(sattn[2][k], t, u2);
            u3 = fmaf(sattn[3][k], t, u3);
        }
        s_av[p][c]        = av;
        s_u[p][c]         = u0;
        s_u[p][CH   + c]  = u1;
        s_u[p][2*CH + c]  = u2;
        s_u[p][3*CH + c]  = u3;
        __syncthreads();
    }

    // fused pe projection: out_c = av_c + sum_j u[h,j] * w_d2[j,c] + b_d2[c]
    // w_d2 read once per block (256 KB, L2-resident), amortized over AP points
    float acc[AP];
    #pragma unroll
    for (int p = 0; p < AP; p++) acc[p] = 0.f;
    int uoff = h * CH;
    #pragma unroll 4
    for (int j = 0; j < CH; j++) {
        float w = __ldg(&w_d2[j*CH + c]);
        #pragma unroll
        for (int p = 0; p < AP; p++)
            acc[p] = fmaf(s_u[p][uoff + j], w, acc[p]);
    }
    float bd2 = b_d2[c];
    #pragma unroll
    for (int p = 0; p < AP; p++)
        xattn[(size_t)(base + p)*CH + c] = s_av[p][c] + acc[p] + bd2;
}

// -------------------- launch ----------------------------------------------
extern "C" void kernel_launch(void* const* d_in, const int* in_sizes, int n_in,
                              void* d_out, int out_size)
{
    const float* xyz      = (const float*)d_in[0];
    const float* xy_embed = (const float*)d_in[1];
    const int*   nns      = (const int*)  d_in[2];
    const float* ln1_g    = (const float*)d_in[3];
    const float* ln1_b    = (const float*)d_in[4];
    const float* w_qkv    = (const float*)d_in[5];
    const float* w_d1     = (const float*)d_in[6];
    const float* b_d1     = (const float*)d_in[7];
    const float* w_d2     = (const float*)d_in[8];
    const float* b_d2     = (const float*)d_in[9];
    const float* w_proj   = (const float*)d_in[10];
    const float* b_proj   = (const float*)d_in[11];
    const float* ln2_g    = (const float*)d_in[12];
    const float* ln2_b    = (const float*)d_in[13];
    const float* w_m1     = (const float*)d_in[14];
    const float* b_m1     = (const float*)d_in[15];
    const float* w_m2     = (const float*)d_in[16];
    const float* b_m2     = (const float*)d_in[17];
    float* out = (float*)d_out;

    float *h, *qkv, *xattn, *x, *mlp1;
    cudaGetSymbolAddress((void**)&h,     g_h);
    cudaGetSymbolAddress((void**)&qkv,   g_qkv);
    cudaGetSymbolAddress((void**)&xattn, g_xattn);
    cudaGetSymbolAddress((void**)&x,     g_x);
    cudaGetSymbolAddress((void**)&mlp1,  g_mlp1);

    // 1. LN1
    ln_kernel<<<NPTS, 256>>>(xy_embed, ln1_g, ln1_b, h);
    // 2. qkv = h @ w_qkv            (32768 x 256 x 768)
    sgemm<0><<<dim3(QKVW/128, NPTS/128), 256>>>(h, w_qkv, qkv, NPTS, QKVW, CH,
                                                nullptr, nullptr);
    // 3. KNN attention + fused pe
    attn_kernel<<<NPTS/AP, 256>>>(qkv, nns, xyz, w_d1, b_d1, w_d2, b_d2, xattn);
    // 4. x = xy_embed + xattn @ w_proj + b_proj
    sgemm<1><<<dim3(CH/128, NPTS/128), 256>>>(xattn, w_proj, x, NPTS, CH, CH,
                                              b_proj, xy_embed);
    // 5. LN2 (reuse h)
    ln_kernel<<<NPTS, 256>>>(x, ln2_g, ln2_b, h);
    // 6. mlp1 = gelu(h @ w_m1 + b_m1)   (32768 x 256 x 1024)
    sgemm<2><<<dim3(1024/128, NPTS/128), 256>>>(h, w_m1, mlp1, NPTS, 1024, CH,
                                                b_m1, nullptr);
    // 7. out = x + mlp1 @ w_m2 + b_m2   (32768 x 1024 x 256)
    sgemm<1><<<dim3(CH/128, NPTS/128), 256>>>(mlp1, w_m2, out, NPTS, CH, 1024,
                                              b_m2, x);
}

// round 5
// speedup vs baseline: 1.5357x; 1.5357x over previous
#include <cuda_runtime.h>
#include <math.h>
#include <stdint.h>

#define BSZ   4
#define NPT   8192
#define CH    256
#define NPTS  (BSZ*NPT)      // 32768
#define QKVW  768
#define AP    8              // points per attention block

// -------------------- scratch (device globals; no cudaMalloc allowed) -----
__device__ float g_h[NPTS*CH];        // LN1 out, reused as LN2 out
__device__ float g_qkv[NPTS*QKVW];
__device__ float g_xattn[NPTS*CH];
__device__ float g_x[NPTS*CH];        // residual stream
__device__ float g_mlp1[NPTS*1024];

// -------------------- LayerNorm (one row per 256-thread block) ------------
__global__ void ln_kernel(const float* __restrict__ x, const float* __restrict__ g,
                          const float* __restrict__ b, float* __restrict__ out)
{
    int row = blockIdx.x;
    int c   = threadIdx.x;
    float v = x[row*CH + c];

    __shared__ float red[8];
    __shared__ float s_mean, s_rstd;

    float s = v;
    #pragma unroll
    for (int o = 16; o > 0; o >>= 1) s += __shfl_xor_sync(0xffffffffu, s, o);
    if ((c & 31) == 0) red[c >> 5] = s;
    __syncthreads();
    if (c == 0) {
        float t = 0.f;
        #pragma unroll
        for (int i = 0; i < 8; i++) t += red[i];
        s_mean = t * (1.0f / CH);
    }
    __syncthreads();
    float m = s_mean;
    float d = v - m;
    s = d * d;
    #pragma unroll
    for (int o = 16; o > 0; o >>= 1) s += __shfl_xor_sync(0xffffffffu, s, o);
    if ((c & 31) == 0) red[c >> 5] = s;
    __syncthreads();
    if (c == 0) {
        float t = 0.f;
        #pragma unroll
        for (int i = 0; i < 8; i++) t += red[i];
        s_rstd = rsqrtf(t * (1.0f / CH) + 1e-5f);
    }
    __syncthreads();
    out[row*CH + c] = d * s_rstd * g[c] + b[c];
}

// -------------------- tf32 tensor-core GEMM -------------------------------
// 128x128x16 tile, 256 threads = 8 warps in 2(M)x4(N), warp tile 64x32 via
// mma.sync.m16n8k8.tf32. fp32 -> tf32 conversion (cvt.rna) happens once at
// the global->smem staging step; accumulation is fp32.
// EPI: 0 = none, 1 = +bias[col] +resid, 2 = gelu(acc + bias[col])
__device__ __forceinline__ float gelu_exact(float v) { return v * normcdff(v); }

__device__ __forceinline__ uint32_t f2tf(float v) {
    uint32_t r;
    asm("cvt.rna.tf32.f32 %0, %1;" : "=r"(r) : "f"(v));
    return r;
}

__device__ __forceinline__ void mma_tf32(float* c,
    uint32_t a0, uint32_t a1, uint32_t a2, uint32_t a3,
    uint32_t b0, uint32_t b1)
{
    asm volatile(
        "mma.sync.aligned.m16n8k8.row.col.f32.tf32.tf32.f32 "
        "{%0,%1,%2,%3}, {%4,%5,%6,%7}, {%8,%9}, {%0,%1,%2,%3};"
        : "+f"(c[0]), "+f"(c[1]), "+f"(c[2]), "+f"(c[3])
        : "r"(a0), "r"(a1), "r"(a2), "r"(a3), "r"(b0), "r"(b1));
}

#define TBM 128
#define TBN 128
#define TBK 16
#define TPAD 8   // stride 136: fragment loads are bank-conflict-free

template<int EPI>
__global__ void __launch_bounds__(256)
tgemm(const float* __restrict__ A, const float* __restrict__ B,
      float* __restrict__ C, int M, int N, int K,
      const float* __restrict__ bias, const float* __restrict__ resid)
{
    __shared__ uint32_t As[2][TBK][TBM + TPAD];
    __shared__ uint32_t Bs[2][TBK][TBN + TPAD];

    int tid  = threadIdx.x;
    int lane = tid & 31;
    int warp = tid >> 5;
    int wm   = warp & 1;      // 2 warps over M
    int wn   = warp >> 1;     // 4 warps over N
    int bm   = blockIdx.y * TBM;
    int bn   = blockIdx.x * TBN;

    const float* Ag = A + (size_t)bm * K;
    const float* Bg = B + bn;

    float acc[4][4][4];
    #pragma unroll
    for (int i = 0; i < 4; i++)
        #pragma unroll
        for (int j = 0; j < 4; j++)
            #pragma unroll
            for (int r = 0; r < 4; r++) acc[i][j][r] = 0.f;

    int nt = K / TBK;

    float4 ra[2], rb[2];
    auto glo = [&](int kt) {
        #pragma unroll
        for (int t = 0; t < 2; t++) {
            int idx = tid * 2 + t;
            int ar = idx >> 2, ac = (idx & 3) * 4;          // A: 128 rows x 16 k
            ra[t] = *(const float4*)(Ag + (size_t)ar * K + kt * TBK + ac);
            int bk = idx >> 5, bn4 = (idx & 31) * 4;        // B: 16 k x 128 n
            rb[t] = *(const float4*)(Bg + (size_t)(kt * TBK + bk) * N + bn4);
        }
    };
    auto sto = [&](int buf) {
        #pragma unroll
        for (int t = 0; t < 2; t++) {
            int idx = tid * 2 + t;
            int ar = idx >> 2, ac = (idx & 3) * 4;
            As[buf][ac + 0][ar] = f2tf(ra[t].x);
            As[buf][ac + 1][ar] = f2tf(ra[t].y);
            As[buf][ac + 2][ar] = f2tf(ra[t].z);
            As[buf][ac + 3][ar] = f2tf(ra[t].w);
            int bk = idx >> 5, bn4 = (idx & 31) * 4;
            Bs[buf][bk][bn4 + 0] = f2tf(rb[t].x);
            Bs[buf][bk][bn4 + 1] = f2tf(rb[t].y);
            Bs[buf][bk][bn4 + 2] = f2tf(rb[t].z);
            Bs[buf][bk][bn4 + 3] = f2tf(rb[t].w);
        }
    };

    glo(0); sto(0);
    __syncthreads();

    for (int kt = 0; kt < nt; kt++) {
        int cur = kt & 1;
        if (kt + 1 < nt) glo(kt + 1);

        #pragma unroll
        for (int kk = 0; kk < TBK; kk += 8) {
            int kq = kk + (lane & 3);
            uint32_t af[4][4], bf[4][2];
            #pragma unroll
            for (int i = 0; i < 4; i++) {
                int m0 = wm * 64 + i * 16 + (lane >> 2);
                af[i][0] = As[cur][kq    ][m0];
                af[i][1] = As[cur][kq    ][m0 + 8];
                af[i][2] = As[cur][kq + 4][m0];
                af[i][3] = As[cur][kq + 4][m0 + 8];
            }
            #pragma unroll
            for (int j = 0; j < 4; j++) {
                int n0 = wn * 32 + j * 8 + (lane >> 2);
                bf[j][0] = Bs[cur][kq    ][n0];
                bf[j][1] = Bs[cur][kq + 4][n0];
            }
            #pragma unroll
            for (int i = 0; i < 4; i++)
                #pragma unroll
                for (int j = 0; j < 4; j++)
                    mma_tf32(acc[i][j], af[i][0], af[i][1], af[i][2], af[i][3],
                             bf[j][0], bf[j][1]);
        }

        if (kt + 1 < nt) sto(cur ^ 1);
        __syncthreads();
    }

    // epilogue: c0/c1 at (row, col..col+1), c2/c3 at (row+8, col..col+1)
    #pragma unroll
    for (int i = 0; i < 4; i++) {
        int row = bm + wm * 64 + i * 16 + (lane >> 2);
        #pragma unroll
        for (int j = 0; j < 4; j++) {
            int col = bn + wn * 32 + j * 8 + (lane & 3) * 2;
            float2 v0 = make_float2(acc[i][j][0], acc[i][j][1]);
            float2 v1 = make_float2(acc[i][j][2], acc[i][j][3]);
            if (EPI >= 1) {
                float2 bv = *(const float2*)&bias[col];
                v0.x += bv.x; v0.y += bv.y;
                v1.x += bv.x; v1.y += bv.y;
            }
            if (EPI == 1) {
                float2 r0 = *(const float2*)&resid[(size_t)row * N + col];
                float2 r1 = *(const float2*)&resid[(size_t)(row + 8) * N + col];
                v0.x += r0.x; v0.y += r0.y;
                v1.x += r1.x; v1.y += r1.y;
            }
            if (EPI == 2) {
                v0.x = gelu_exact(v0.x); v0.y = gelu_exact(v0.y);
                v1.x = gelu_exact(v1.x); v1.y = gelu_exact(v1.y);
            }
            *(float2*)&C[(size_t)row * N + col]       = v0;
            *(float2*)&C[(size_t)(row + 8) * N + col] = v1;
        }
    }
}

// -------------------- KNN attention + fused pe projection -----------------
__global__ void __launch_bounds__(256)
attn_kernel(const float* __restrict__ qkv, const int* __restrict__ nns,
            const float* __restrict__ xyz,
            const float* __restrict__ w_d1, const float* __restrict__ b_d1,
            const float* __restrict__ w_d2, const float* __restrict__ b_d2,
            float* __restrict__ xattn)
{
    __shared__ float sq[CH];
    __shared__ int   snbr[16];
    __shared__ float srelx[16], srely[16];
    __shared__ float spart[16][8];
    __shared__ float sattn[4][16];
    __shared__ float s_u[AP][4*CH];   // 32 KB
    __shared__ float s_av[AP][CH];    // 8 KB

    int c    = threadIdx.x;
    int h    = c >> 6;
    int lane = c & 31;
    int warp = c >> 5;

    float wd1x = w_d1[c];
    float wd1y = w_d1[CH + c];
    float bd1  = b_d1[c];

    int base = blockIdx.x * AP;

    for (int p = 0; p < AP; p++) {
        int pi = base + p;
        int bb = pi >> 13;                      // batch index (N = 8192)

        if (c < 16) {
            int j   = nns[pi*32 + c];           // first K=16 of NN=32
            int row = (bb << 13) + j;
            snbr[c]  = row;
            srelx[c] = xyz[pi*2]     - xyz[row*2];
            srely[c] = xyz[pi*2 + 1] - xyz[row*2 + 1];
        }
        sq[c] = qkv[(size_t)pi*QKVW + c];
        __syncthreads();

        #pragma unroll
        for (int k = 0; k < 16; k++) {
            float pr = qkv[(size_t)snbr[k]*QKVW + CH + c] * sq[c];
            #pragma unroll
            for (int o = 16; o > 0; o >>= 1)
                pr += __shfl_xor_sync(0xffffffffu, pr, o);
            if (lane == 0) spart[k][warp] = pr;
        }
        __syncthreads();
        if (c < 64) {
            int k = c & 15, hh = c >> 4;
            sattn[hh][k] = (spart[k][2*hh] + spart[k][2*hh + 1]) * 0.125f;
        }
        __syncthreads();
        if (c < 4) {
            float mx = -1e30f;
            #pragma unroll
            for (int k = 0; k < 16; k++) mx = fmaxf(mx, sattn[c][k]);
            float sm = 0.f;
            #pragma unroll
            for (int k = 0; k < 16; k++) {
                float e = __expf(sattn[c][k] - mx);
                sattn[c][k] = e; sm += e;
            }
            float inv = 1.f / sm;
            #pragma unroll
            for (int k = 0; k < 16; k++) sattn[c][k] *= inv;
        }
        __syncthreads();

        float av = 0.f, u0 = 0.f, u1 = 0.f, u2 = 0.f, u3 = 0.f;
        #pragma unroll
        for (int k = 0; k < 16; k++) {
            float v = qkv[(size_t)snbr[k]*QKVW + 2*CH + c];
            av = fmaf(sattn[h][k], v, av);
            float t = fmaxf(fmaf(srelx[k], wd1x, fmaf(srely[k], wd1y, bd1)), 0.f);
            u0 = fmaf(sattn[0][k], t, u0);
            u1 = fmaf(sattn[1][k], t, u1);
            u2 = fmaf(sattn[2][k], t, u2);
            u3 = fmaf(sattn[3][k], t, u3);
        }
        s_av[p][c]        = av;
        s_u[p][c]         = u0;
        s_u[p][CH   + c]  = u1;
        s_u[p][2*CH + c]  = u2;
        s_u[p][3*CH + c]  = u3;
        __syncthreads();
    }

    // fused pe projection: out_c = av_c + sum_j u[h,j] * w_d2[j,c] + b_d2[c]
    float acc[AP];
    #pragma unroll
    for (int p = 0; p < AP; p++) acc[p] = 0.f;
    int uoff = h * CH;
    #pragma unroll 4
    for (int j = 0; j < CH; j++) {
        float w = __ldg(&w_d2[j*CH + c]);
        #pragma unroll
        for (int p = 0; p < AP; p++)
            acc[p] = fmaf(s_u[p][uoff + j], w, acc[p]);
    }
    float bd2 = b_d2[c];
    #pragma unroll
    for (int p = 0; p < AP; p++)
        xattn[(size_t)(base + p)*CH + c] = s_av[p][c] + acc[p] + bd2;
}

// -------------------- launch ----------------------------------------------
extern "C" void kernel_launch(void* const* d_in, const int* in_sizes, int n_in,
                              void* d_out, int out_size)
{
    const float* xyz      = (const float*)d_in[0];
    const float* xy_embed = (const float*)d_in[1];
    const int*   nns      = (const int*)  d_in[2];
    const float* ln1_g    = (const float*)d_in[3];
    const float* ln1_b    = (const float*)d_in[4];
    const float* w_qkv    = (const float*)d_in[5];
    const float* w_d1     = (const float*)d_in[6];
    const float* b_d1     = (const float*)d_in[7];
    const float* w_d2     = (const float*)d_in[8];
    const float* b_d2     = (const float*)d_in[9];
    const float* w_proj   = (const float*)d_in[10];
    const float* b_proj   = (const float*)d_in[11];
    const float* ln2_g    = (const float*)d_in[12];
    const float* ln2_b    = (const float*)d_in[13];
    const float* w_m1     = (const float*)d_in[14];
    const float* b_m1     = (const float*)d_in[15];
    const float* w_m2     = (const float*)d_in[16];
    const float* b_m2     = (const float*)d_in[17];
    float* out = (float*)d_out;

    float *h, *qkv, *xattn, *x, *mlp1;
    cudaGetSymbolAddress((void**)&h,     g_h);
    cudaGetSymbolAddress((void**)&qkv,   g_qkv);
    cudaGetSymbolAddress((void**)&xattn, g_xattn);
    cudaGetSymbolAddress((void**)&x,     g_x);
    cudaGetSymbolAddress((void**)&mlp1,  g_mlp1);

    // 1. LN1
    ln_kernel<<<NPTS, 256>>>(xy_embed, ln1_g, ln1_b, h);
    // 2. qkv = h @ w_qkv            (32768 x 768 x 256)
    tgemm<0><<<dim3(QKVW/TBN, NPTS/TBM), 256>>>(h, w_qkv, qkv, NPTS, QKVW, CH,
                                                nullptr, nullptr);
    // 3. KNN attention + fused pe
    attn_kernel<<<NPTS/AP, 256>>>(qkv, nns, xyz, w_d1, b_d1, w_d2, b_d2, xattn);
    // 4. x = xy_embed + xattn @ w_proj + b_proj
    tgemm<1><<<dim3(CH/TBN, NPTS/TBM), 256>>>(xattn, w_proj, x, NPTS, CH, CH,
                                              b_proj, xy_embed);
    // 5. LN2 (reuse h)
    ln_kernel<<<NPTS, 256>>>(x, ln2_g, ln2_b, h);
    // 6. mlp1 = gelu(h @ w_m1 + b_m1)   (32768 x 1024 x 256)
    tgemm<2><<<dim3(1024/TBN, NPTS/TBM), 256>>>(h, w_m1, mlp1, NPTS, 1024, CH,
                                                b_m1, nullptr);
    // 7. out = x + mlp1 @ w_m2 + b_m2   (32768 x 256 x 1024)
    tgemm<1><<<dim3(CH/TBN, NPTS/TBM), 256>>>(mlp1, w_m2, out, NPTS, CH, 1024,
                                              b_m2, x);
}

// round 6
// speedup vs baseline: 2.0046x; 1.3054x over previous
#include <cuda_runtime.h>
#include <cuda_fp16.h>
#include <math.h>
#include <stdint.h>

#define BSZ   4
#define NPT   8192
#define CH    256
#define NPTS  (BSZ*NPT)      // 32768
#define QKVW  768
#define AP    8              // points per attention block

// -------------------- scratch (device globals; no cudaMalloc allowed) -----
__device__ __half g_h[NPTS*CH];          // LN out (half, feeds GEMMs)
__device__ __half g_qkvh[NPTS*QKVW];     // qkv in half
__device__ __half g_xattn[NPTS*CH];
__device__ float  g_x[NPTS*CH];          // residual stream (fp32)
__device__ __half g_mlp1[NPTS*1024];
__device__ __half g_wqkv16[CH*QKVW];
__device__ __half g_wproj16[CH*CH];
__device__ __half g_wm1_16[CH*1024];
__device__ __half g_wm2_16[1024*CH];

// -------------------- fp32 -> fp16 weight conversion ----------------------
__global__ void f2h_kernel(const float* __restrict__ src, __half* __restrict__ dst, int n)
{
    int i = blockIdx.x * 256 + threadIdx.x;
    if (i < n) dst[i] = __float2half(src[i]);
}

// -------------------- LayerNorm (fp32 in, fp16 out) -----------------------
__global__ void ln_kernel(const float* __restrict__ x, const float* __restrict__ g,
                          const float* __restrict__ b, __half* __restrict__ out)
{
    int row = blockIdx.x;
    int c   = threadIdx.x;
    float v = x[row*CH + c];

    __shared__ float red[8];
    __shared__ float s_mean, s_rstd;

    float s = v;
    #pragma unroll
    for (int o = 16; o > 0; o >>= 1) s += __shfl_xor_sync(0xffffffffu, s, o);
    if ((c & 31) == 0) red[c >> 5] = s;
    __syncthreads();
    if (c == 0) {
        float t = 0.f;
        #pragma unroll
        for (int i = 0; i < 8; i++) t += red[i];
        s_mean = t * (1.0f / CH);
    }
    __syncthreads();
    float m = s_mean;
    float d = v - m;
    s = d * d;
    #pragma unroll
    for (int o = 16; o > 0; o >>= 1) s += __shfl_xor_sync(0xffffffffu, s, o);
    if ((c & 31) == 0) red[c >> 5] = s;
    __syncthreads();
    if (c == 0) {
        float t = 0.f;
        #pragma unroll
        for (int i = 0; i < 8; i++) t += red[i];
        s_rstd = rsqrtf(t * (1.0f / CH) + 1e-5f);
    }
    __syncthreads();
    out[row*CH + c] = __float2half(d * s_rstd * g[c] + b[c]);
}

// -------------------- fp16 tensor-core GEMM -------------------------------
// 128x128x32 tile, 256 threads = 8 warps (2M x 4N), warp tile 64x32.
// cp.async 16B staging, ldmatrix fragments, mma.m16n8k16.f16 with fp32 acc.
// EPI: 0 = none, 1 = +bias +resid, 2 = gelu(acc + bias)
__device__ __forceinline__ float gelu_exact(float v) { return v * normcdff(v); }

#define HBM 128
#define HBN 128
#define HBK 32
#define APAD 8   // halves; A row stride 40h=80B -> ldmatrix rows conflict-free
#define BPAD 8   // halves; B row stride 136h=272B -> conflict-free

__device__ __forceinline__ void mma16816(float* c, const uint32_t* a,
                                         uint32_t b0, uint32_t b1)
{
    asm volatile(
        "mma.sync.aligned.m16n8k16.row.col.f32.f16.f16.f32 "
        "{%0,%1,%2,%3}, {%4,%5,%6,%7}, {%8,%9}, {%0,%1,%2,%3};"
        : "+f"(c[0]), "+f"(c[1]), "+f"(c[2]), "+f"(c[3])
        : "r"(a[0]), "r"(a[1]), "r"(a[2]), "r"(a[3]), "r"(b0), "r"(b1));
}

template<int EPI, typename OutT>
__global__ void __launch_bounds__(256)
hgemm(const __half* __restrict__ A, const __half* __restrict__ B,
      OutT* __restrict__ C, int M, int N, int K,
      const float* __restrict__ bias, const float* __restrict__ resid)
{
    __shared__ __half As[2][HBM][HBK + APAD];
    __shared__ __half Bs[2][HBK][HBN + BPAD];

    int tid  = threadIdx.x;
    int lane = tid & 31;
    int warp = tid >> 5;
    int wm   = warp & 1;
    int wn   = warp >> 1;
    int bm   = blockIdx.y * HBM;
    int bn   = blockIdx.x * HBN;

    const __half* Ag = A + (size_t)bm * K;
    const __half* Bg = B + bn;

    float acc[4][4][4];
    #pragma unroll
    for (int i = 0; i < 4; i++)
        #pragma unroll
        for (int j = 0; j < 4; j++)
            #pragma unroll
            for (int r = 0; r < 4; r++) acc[i][j][r] = 0.f;

    auto issue = [&](int kt, int buf) {
        #pragma unroll
        for (int s = 0; s < 2; s++) {
            int c  = tid * 2 + s;
            int ar = c >> 2, ak = (c & 3) * 8;                 // A: 128r x 32k
            uint32_t da = (uint32_t)__cvta_generic_to_shared(&As[buf][ar][ak]);
            const __half* ga = Ag + (size_t)ar * K + kt * HBK + ak;
            asm volatile("cp.async.cg.shared.global [%0], [%1], 16;\n"
                         :: "r"(da), "l"(ga));
            int bk = c >> 4, bnn = (c & 15) * 8;               // B: 32k x 128n
            uint32_t db = (uint32_t)__cvta_generic_to_shared(&Bs[buf][bk][bnn]);
            const __half* gb = Bg + (size_t)(kt * HBK + bk) * N + bnn;
            asm volatile("cp.async.cg.shared.global [%0], [%1], 16;\n"
                         :: "r"(db), "l"(gb));
        }
        asm volatile("cp.async.commit_group;\n");
    };

    issue(0, 0);
    asm volatile("cp.async.wait_group 0;\n");
    __syncthreads();

    int nt = K / HBK;
    for (int kt = 0; kt < nt; kt++) {
        int cur = kt & 1;
        if (kt + 1 < nt) issue(kt + 1, cur ^ 1);

        #pragma unroll
        for (int kk = 0; kk < HBK; kk += 16) {
            uint32_t af[4][4];
            #pragma unroll
            for (int i = 0; i < 4; i++) {
                int row = wm * 64 + i * 16 + (lane & 15);
                int kc  = kk + (lane >> 4) * 8;
                uint32_t ad = (uint32_t)__cvta_generic_to_shared(&As[cur][row][kc]);
                asm volatile(
                    "ldmatrix.sync.aligned.m8n8.x4.shared.b16 {%0,%1,%2,%3}, [%4];"
                    : "=r"(af[i][0]), "=r"(af[i][1]), "=r"(af[i][2]), "=r"(af[i][3])
                    : "r"(ad));
            }
            #pragma unroll
            for (int j = 0; j < 2; j++) {
                uint32_t bf[4];
                int krow = kk + (lane & 15);
                int nc   = wn * 32 + j * 16 + (lane >> 4) * 8;
                uint32_t bd = (uint32_t)__cvta_generic_to_shared(&Bs[cur][krow][nc]);
                asm volatile(
                    "ldmatrix.sync.aligned.m8n8.x4.trans.shared.b16 {%0,%1,%2,%3}, [%4];"
                    : "=r"(bf[0]), "=r"(bf[1]), "=r"(bf[2]), "=r"(bf[3])
                    : "r"(bd));
                #pragma unroll
                for (int i = 0; i < 4; i++) {
                    mma16816(acc[i][2*j],     af[i], bf[0], bf[1]);
                    mma16816(acc[i][2*j + 1], af[i], bf[2], bf[3]);
                }
            }
        }

        if (kt + 1 < nt) asm volatile("cp.async.wait_group 0;\n");
        __syncthreads();
    }

    // epilogue: acc[i][jj]: rows (r, r+8), cols col..col+1
    #pragma unroll
    for (int i = 0; i < 4; i++) {
        int row = bm + wm * 64 + i * 16 + (lane >> 2);
        #pragma unroll
        for (int jj = 0; jj < 4; jj++) {
            int col = bn + wn * 32 + (jj >> 1) * 16 + (jj & 1) * 8 + (lane & 3) * 2;
            float2 v0 = make_float2(acc[i][jj][0], acc[i][jj][1]);
            float2 v1 = make_float2(acc[i][jj][2], acc[i][jj][3]);
            if (EPI >= 1) {
                float2 bv = *(const float2*)&bias[col];
                v0.x += bv.x; v0.y += bv.y;
                v1.x += bv.x; v1.y += bv.y;
            }
            if (EPI == 1) {
                float2 r0 = *(const float2*)&resid[(size_t)row * N + col];
                float2 r1 = *(const float2*)&resid[(size_t)(row + 8) * N + col];
                v0.x += r0.x; v0.y += r0.y;
                v1.x += r1.x; v1.y += r1.y;
            }
            if (EPI == 2) {
                v0.x = gelu_exact(v0.x); v0.y = gelu_exact(v0.y);
                v1.x = gelu_exact(v1.x); v1.y = gelu_exact(v1.y);
            }
            if constexpr (sizeof(OutT) == 2) {
                *(__half2*)&C[(size_t)row * N + col]       = __floats2half2_rn(v0.x, v0.y);
                *(__half2*)&C[(size_t)(row + 8) * N + col] = __floats2half2_rn(v1.x, v1.y);
            } else {
                *(float2*)&C[(size_t)row * N + col]       = v0;
                *(float2*)&C[(size_t)(row + 8) * N + col] = v1;
            }
        }
    }
}

// -------------------- KNN attention + fused pe projection -----------------
__global__ void __launch_bounds__(256)
attn_kernel(const __half* __restrict__ qkv, const int* __restrict__ nns,
            const float* __restrict__ xyz,
            const float* __restrict__ w_d1, const float* __restrict__ b_d1,
            const float* __restrict__ w_d2, const float* __restrict__ b_d2,
            __half* __restrict__ xattn)
{
    __shared__ float sq[CH];
    __shared__ int   snbr[16];
    __shared__ float srelx[16], srely[16];
    __shared__ float spart[16][8];
    __shared__ float sattn[4][16];
    __shared__ float s_u[AP][4*CH];   // 32 KB
    __shared__ float s_av[AP][CH];    // 8 KB

    int c    = threadIdx.x;
    int h    = c >> 6;
    int lane = c & 31;
    int warp = c >> 5;

    float wd1x = w_d1[c];
    float wd1y = w_d1[CH + c];
    float bd1  = b_d1[c];

    int base = blockIdx.x * AP;

    for (int p = 0; p < AP; p++) {
        int pi = base + p;
        int bb = pi >> 13;                      // batch index (N = 8192)

        if (c < 16) {
            int j   = nns[pi*32 + c];           // first K=16 of NN=32
            int row = (bb << 13) + j;
            snbr[c]  = row;
            srelx[c] = xyz[pi*2]     - xyz[row*2];
            srely[c] = xyz[pi*2 + 1] - xyz[row*2 + 1];
        }
        sq[c] = __half2float(qkv[(size_t)pi*QKVW + c]);
        __syncthreads();

        #pragma unroll
        for (int k = 0; k < 16; k++) {
            float pr = __half2float(qkv[(size_t)snbr[k]*QKVW + CH + c]) * sq[c];
            #pragma unroll
            for (int o = 16; o > 0; o >>= 1)
                pr += __shfl_xor_sync(0xffffffffu, pr, o);
            if (lane == 0) spart[k][warp] = pr;
        }
        __syncthreads();
        if (c < 64) {
            int k = c & 15, hh = c >> 4;
            sattn[hh][k] = (spart[k][2*hh] + spart[k][2*hh + 1]) * 0.125f;
        }
        __syncthreads();
        if (c < 4) {
            float mx = -1e30f;
            #pragma unroll
            for (int k = 0; k < 16; k++) mx = fmaxf(mx, sattn[c][k]);
            float sm = 0.f;
            #pragma unroll
            for (int k = 0; k < 16; k++) {
                float e = __expf(sattn[c][k] - mx);
                sattn[c][k] = e; sm += e;
            }
            float inv = 1.f / sm;
            #pragma unroll
            for (int k = 0; k < 16; k++) sattn[c][k] *= inv;
        }
        __syncthreads();

        float av = 0.f, u0 = 0.f, u1 = 0.f, u2 = 0.f, u3 = 0.f;
        #pragma unroll
        for (int k = 0; k < 16; k++) {
            float v = __half2float(qkv[(size_t)snbr[k]*QKVW + 2*CH + c]);
            av = fmaf(sattn[h][k], v, av);
            float t = fmaxf(fmaf(srelx[k], wd1x, fmaf(srely[k], wd1y, bd1)), 0.f);
            u0 = fmaf(sattn[0][k], t, u0);
            u1 = fmaf(sattn[1][k], t, u1);
            u2 = fmaf(sattn[2][k], t, u2);
            u3 = fmaf(sattn[3][k], t, u3);
        }
        s_av[p][c]        = av;
        s_u[p][c]         = u0;
        s_u[p][CH   + c]  = u1;
        s_u[p][2*CH + c]  = u2;
        s_u[p][3*CH + c]  = u3;
        __syncthreads();
    }

    // fused pe projection
    float acc[AP];
    #pragma unroll
    for (int p = 0; p < AP; p++) acc[p] = 0.f;
    int uoff = h * CH;
    #pragma unroll 4
    for (int j = 0; j < CH; j++) {
        float w = __ldg(&w_d2[j*CH + c]);
        #pragma unroll
        for (int p = 0; p < AP; p++)
            acc[p] = fmaf(s_u[p][uoff + j], w, acc[p]);
    }
    float bd2 = b_d2[c];
    #pragma unroll
    for (int p = 0; p < AP; p++)
        xattn[(size_t)(base + p)*CH + c] =
            __float2half(s_av[p][c] + acc[p] + bd2);
}

// -------------------- launch ----------------------------------------------
extern "C" void kernel_launch(void* const* d_in, const int* in_sizes, int n_in,
                              void* d_out, int out_size)
{
    const float* xyz      = (const float*)d_in[0];
    const float* xy_embed = (const float*)d_in[1];
    const int*   nns      = (const int*)  d_in[2];
    const float* ln1_g    = (const float*)d_in[3];
    const float* ln1_b    = (const float*)d_in[4];
    const float* w_qkv    = (const float*)d_in[5];
    const float* w_d1     = (const float*)d_in[6];
    const float* b_d1     = (const float*)d_in[7];
    const float* w_d2     = (const float*)d_in[8];
    const float* b_d2     = (const float*)d_in[9];
    const float* w_proj   = (const float*)d_in[10];
    const float* b_proj   = (const float*)d_in[11];
    const float* ln2_g    = (const float*)d_in[12];
    const float* ln2_b    = (const float*)d_in[13];
    const float* w_m1     = (const float*)d_in[14];
    const float* b_m1     = (const float*)d_in[15];
    const float* w_m2     = (const float*)d_in[16];
    const float* b_m2     = (const float*)d_in[17];
    float* out = (float*)d_out;

    __half *h, *qkvh, *xattn, *mlp1, *wqkv16, *wproj16, *wm1_16, *wm2_16;
    float *x;
    cudaGetSymbolAddress((void**)&h,       g_h);
    cudaGetSymbolAddress((void**)&qkvh,    g_qkvh);
    cudaGetSymbolAddress((void**)&xattn,   g_xattn);
    cudaGetSymbolAddress((void**)&x,       g_x);
    cudaGetSymbolAddress((void**)&mlp1,    g_mlp1);
    cudaGetSymbolAddress((void**)&wqkv16,  g_wqkv16);
    cudaGetSymbolAddress((void**)&wproj16, g_wproj16);
    cudaGetSymbolAddress((void**)&wm1_16,  g_wm1_16);
    cudaGetSymbolAddress((void**)&wm2_16,  g_wm2_16);

    // 0. weight conversions (independent, tiny)
    f2h_kernel<<<(CH*QKVW + 255)/256, 256>>>(w_qkv, wqkv16, CH*QKVW);
    f2h_kernel<<<(CH*CH   + 255)/256, 256>>>(w_proj, wproj16, CH*CH);
    f2h_kernel<<<(CH*1024 + 255)/256, 256>>>(w_m1, wm1_16, CH*1024);
    f2h_kernel<<<(1024*CH + 255)/256, 256>>>(w_m2, wm2_16, 1024*CH);

    // 1. LN1 -> half
    ln_kernel<<<NPTS, 256>>>(xy_embed, ln1_g, ln1_b, h);
    // 2. qkv = h @ w_qkv  (32768 x 768 x 256), half out
    hgemm<0, __half><<<dim3(QKVW/HBN, NPTS/HBM), 256>>>(h, wqkv16, qkvh,
        NPTS, QKVW, CH, nullptr, nullptr);
    // 3. KNN attention + fused pe -> half
    attn_kernel<<<NPTS/AP, 256>>>(qkvh, nns, xyz, w_d1, b_d1, w_d2, b_d2, xattn);
    // 4. x = xy_embed + xattn @ w_proj + b_proj  (fp32 residual)
    hgemm<1, float><<<dim3(CH/HBN, NPTS/HBM), 256>>>(xattn, wproj16, x,
        NPTS, CH, CH, b_proj, xy_embed);
    // 5. LN2 -> half
    ln_kernel<<<NPTS, 256>>>(x, ln2_g, ln2_b, h);
    // 6. mlp1 = gelu(h @ w_m1 + b_m1)  (32768 x 1024 x 256), half out
    hgemm<2, __half><<<dim3(1024/HBN, NPTS/HBM), 256>>>(h, wm1_16, mlp1,
        NPTS, 1024, CH, b_m1, nullptr);
    // 7. out = x + mlp1 @ w_m2 + b_m2  (32768 x 256 x 1024), fp32 out
    hgemm<1, float><<<dim3(CH/HBN, NPTS/HBM), 256>>>(mlp1, wm2_16, out,
        NPTS, CH, 1024, b_m2, x);
}

// round 7
// speedup vs baseline: 3.1231x; 1.5579x over previous
#include <cuda_runtime.h>
#include <cuda_fp16.h>
#include <math.h>
#include <stdint.h>

#define BSZ   4
#define NPT   8192
#define CH    256
#define NPTS  (BSZ*NPT)      // 32768
#define QKVW  768
#define AP    8              // points per attention block (one per warp)

// -------------------- scratch (device globals; no cudaMalloc allowed) -----
__device__ __half g_h[NPTS*CH];          // LN out (half, feeds GEMMs)
__device__ __half g_qkvh[NPTS*QKVW];     // qkv in half
__device__ __half g_xattn[NPTS*CH];
__device__ float  g_x[NPTS*CH];          // residual stream (fp32)
__device__ __half g_mlp1[NPTS*1024];
__device__ __half g_wqkv16[CH*QKVW];
__device__ __half g_wproj16[CH*CH];
__device__ __half g_wm1_16[CH*1024];
__device__ __half g_wm2_16[1024*CH];
__device__ __half g_wd2t[CH*CH];         // w_d2 transposed: [c][j], half

// -------------------- small converters ------------------------------------
__global__ void f2h_kernel(const float* __restrict__ src, __half* __restrict__ dst, int n)
{
    int i = blockIdx.x * 256 + threadIdx.x;
    if (i < n) dst[i] = __float2half(src[i]);
}

__global__ void wd2t_kernel(const float* __restrict__ w, __half* __restrict__ wt)
{
    int i = blockIdx.x * 256 + threadIdx.x;   // i = c*256 + j
    int c = i >> 8, j = i & 255;
    wt[i] = __float2half(w[j*CH + c]);
}

// -------------------- LayerNorm (warp per row, fp32 in, fp16 out) ---------
__global__ void __launch_bounds__(256)
ln_kernel(const float* __restrict__ x, const float* __restrict__ g,
          const float* __restrict__ b, __half* __restrict__ out)
{
    int warp = threadIdx.x >> 5, lane = threadIdx.x & 31;
    int row  = blockIdx.x * 8 + warp;
    const float* xr = x + (size_t)row*CH + lane*8;

    float v[8];
    *(float4*)(v)     = *(const float4*)(xr);
    *(float4*)(v + 4) = *(const float4*)(xr + 4);

    float s = 0.f;
    #pragma unroll
    for (int j = 0; j < 8; j++) s += v[j];
    #pragma unroll
    for (int o = 16; o > 0; o >>= 1) s += __shfl_xor_sync(0xffffffffu, s, o);
    float mean = s * (1.0f / CH);

    float d[8], ss = 0.f;
    #pragma unroll
    for (int j = 0; j < 8; j++) { d[j] = v[j] - mean; ss += d[j]*d[j]; }
    #pragma unroll
    for (int o = 16; o > 0; o >>= 1) ss += __shfl_xor_sync(0xffffffffu, ss, o);
    float rstd = rsqrtf(ss * (1.0f / CH) + 1e-5f);

    float gv[8], bv[8];
    *(float4*)(gv)     = *(const float4*)(g + lane*8);
    *(float4*)(gv + 4) = *(const float4*)(g + lane*8 + 4);
    *(float4*)(bv)     = *(const float4*)(b + lane*8);
    *(float4*)(bv + 4) = *(const float4*)(b + lane*8 + 4);

    __half2 o2[4];
    #pragma unroll
    for (int j = 0; j < 4; j++)
        o2[j] = __floats2half2_rn(d[2*j]*rstd*gv[2*j] + bv[2*j],
                                  d[2*j+1]*rstd*gv[2*j+1] + bv[2*j+1]);
    *(uint4*)(out + (size_t)row*CH + lane*8) = *(uint4*)o2;
}

// -------------------- fp16 tensor-core GEMM (3-stage cp.async) ------------
__device__ __forceinline__ float gelu_exact(float v) { return v * normcdff(v); }

#define HBM 128
#define HBN 128
#define HBK 32
#define AS_STR 40     // HBK + 8 halves
#define BS_STR 136    // HBN + 8 halves
#define STAGE_H (HBM*AS_STR + HBK*BS_STR)   // 9472 halves
#define HSMEM_BYTES (3*STAGE_H*2)           // 56832 B

__device__ __forceinline__ void mma16816(float* c, const uint32_t* a,
                                         uint32_t b0, uint32_t b1)
{
    asm volatile(
        "mma.sync.aligned.m16n8k16.row.col.f32.f16.f16.f32 "
        "{%0,%1,%2,%3}, {%4,%5,%6,%7}, {%8,%9}, {%0,%1,%2,%3};"
        : "+f"(c[0]), "+f"(c[1]), "+f"(c[2]), "+f"(c[3])
        : "r"(a[0]), "r"(a[1]), "r"(a[2]), "r"(a[3]), "r"(b0), "r"(b1));
}

template<int EPI, typename OutT>
__global__ void __launch_bounds__(256)
hgemm(const __half* __restrict__ A, const __half* __restrict__ B,
      OutT* __restrict__ C, int M, int N, int K,
      const float* __restrict__ bias, const float* __restrict__ resid)
{
    extern __shared__ __half sh[];

    int tid  = threadIdx.x;
    int lane = tid & 31;
    int warp = tid >> 5;
    int wm   = warp & 1;
    int wn   = warp >> 1;
    int bm   = blockIdx.y * HBM;
    int bn   = blockIdx.x * HBN;

    const __half* Ag = A + (size_t)bm * K;
    const __half* Bg = B + bn;

    float acc[4][4][4];
    #pragma unroll
    for (int i = 0; i < 4; i++)
        #pragma unroll
        for (int j = 0; j < 4; j++)
            #pragma unroll
            for (int r = 0; r < 4; r++) acc[i][j][r] = 0.f;

    auto issue = [&](int kt, int buf) {
        __half* As = sh + buf * STAGE_H;
        __half* Bs = As + HBM * AS_STR;
        #pragma unroll
        for (int s = 0; s < 2; s++) {
            int c  = tid * 2 + s;
            int ar = c >> 2, ak = (c & 3) * 8;
            uint32_t da = (uint32_t)__cvta_generic_to_shared(As + ar*AS_STR + ak);
            const __half* ga = Ag + (size_t)ar * K + kt * HBK + ak;
            asm volatile("cp.async.cg.shared.global [%0], [%1], 16;\n"
                         :: "r"(da), "l"(ga));
            int bk = c >> 4, bnn = (c & 15) * 8;
            uint32_t db = (uint32_t)__cvta_generic_to_shared(Bs + bk*BS_STR + bnn);
            const __half* gb = Bg + (size_t)(kt * HBK + bk) * N + bnn;
            asm volatile("cp.async.cg.shared.global [%0], [%1], 16;\n"
                         :: "r"(db), "l"(gb));
        }
        asm volatile("cp.async.commit_group;\n");
    };

    int nt = K / HBK;
    issue(0, 0);
    issue(1, 1);
    asm volatile("cp.async.wait_group 1;\n");
    __syncthreads();

    for (int kt = 0; kt < nt; kt++) {
        int cur = kt % 3;
        bool more = (kt + 2) < nt;
        if (more) issue(kt + 2, (kt + 2) % 3);

        __half* As = sh + cur * STAGE_H;
        __half* Bs = As + HBM * AS_STR;

        #pragma unroll
        for (int kk = 0; kk < HBK; kk += 16) {
            uint32_t af[4][4];
            #pragma unroll
            for (int i = 0; i < 4; i++) {
                int row = wm * 64 + i * 16 + (lane & 15);
                int kc  = kk + (lane >> 4) * 8;
                uint32_t ad = (uint32_t)__cvta_generic_to_shared(As + row*AS_STR + kc);
                asm volatile(
                    "ldmatrix.sync.aligned.m8n8.x4.shared.b16 {%0,%1,%2,%3}, [%4];"
                    : "=r"(af[i][0]), "=r"(af[i][1]), "=r"(af[i][2]), "=r"(af[i][3])
                    : "r"(ad));
            }
            #pragma unroll
            for (int j = 0; j < 2; j++) {
                uint32_t bf[4];
                int krow = kk + (lane & 15);
                int nc   = wn * 32 + j * 16 + (lane >> 4) * 8;
                uint32_t bd = (uint32_t)__cvta_generic_to_shared(Bs + krow*BS_STR + nc);
                asm volatile(
                    "ldmatrix.sync.aligned.m8n8.x4.trans.shared.b16 {%0,%1,%2,%3}, [%4];"
                    : "=r"(bf[0]), "=r"(bf[1]), "=r"(bf[2]), "=r"(bf[3])
                    : "r"(bd));
                #pragma unroll
                for (int i = 0; i < 4; i++) {
                    mma16816(acc[i][2*j],     af[i], bf[0], bf[1]);
                    mma16816(acc[i][2*j + 1], af[i], bf[2], bf[3]);
                }
            }
        }

        if (more) asm volatile("cp.async.wait_group 1;\n");
        else      asm volatile("cp.async.wait_group 0;\n");
        __syncthreads();
    }

    #pragma unroll
    for (int i = 0; i < 4; i++) {
        int row = bm + wm * 64 + i * 16 + (lane >> 2);
        #pragma unroll
        for (int jj = 0; jj < 4; jj++) {
            int col = bn + wn * 32 + (jj >> 1) * 16 + (jj & 1) * 8 + (lane & 3) * 2;
            float2 v0 = make_float2(acc[i][jj][0], acc[i][jj][1]);
            float2 v1 = make_float2(acc[i][jj][2], acc[i][jj][3]);
            if (EPI >= 1) {
                float2 bv = *(const float2*)&bias[col];
                v0.x += bv.x; v0.y += bv.y;
                v1.x += bv.x; v1.y += bv.y;
            }
            if (EPI == 1) {
                float2 r0 = *(const float2*)&resid[(size_t)row * N + col];
                float2 r1 = *(const float2*)&resid[(size_t)(row + 8) * N + col];
                v0.x += r0.x; v0.y += r0.y;
                v1.x += r1.x; v1.y += r1.y;
            }
            if (EPI == 2) {
                v0.x = gelu_exact(v0.x); v0.y = gelu_exact(v0.y);
                v1.x = gelu_exact(v1.x); v1.y = gelu_exact(v1.y);
            }
            if constexpr (sizeof(OutT) == 2) {
                *(__half2*)&C[(size_t)row * N + col]       = __floats2half2_rn(v0.x, v0.y);
                *(__half2*)&C[(size_t)(row + 8) * N + col] = __floats2half2_rn(v1.x, v1.y);
            } else {
                *(float2*)&C[(size_t)row * N + col]       = v0;
                *(float2*)&C[(size_t)(row + 8) * N + col] = v1;
            }
        }
    }
}

// -------------------- KNN attention: warp per point -----------------------
// Each warp handles one point: lane owns 8 channels (c = lane*8..+7),
// head = lane>>3. Logits via 8-lane-group shfl reduce, softmax in registers,
// v/pe accumulation in registers, then one block-wide half2 projection of
// the hoisted pe basis u through w_d2 (transposed, half).
__global__ void __launch_bounds__(256)
attn_kernel(const __half* __restrict__ qkv, const int* __restrict__ nns,
            const float* __restrict__ xyz,
            const float* __restrict__ w_d1, const float* __restrict__ b_d1,
            const __half* __restrict__ w_d2t, const float* __restrict__ b_d2,
            __half* __restrict__ xattn)
{
    __shared__ __half s_u[AP][4*CH + 8];   // pe basis, half
    __shared__ float  s_av[AP][CH];        // attn-weighted V

    int tid  = threadIdx.x;
    int lane = tid & 31;
    int p    = tid >> 5;
    int pi   = blockIdx.x * AP + p;
    int bb   = pi >> 13;

    int nbr = 0; float rx = 0.f, ry = 0.f;
    if (lane < 16) {
        int j = nns[pi*32 + lane];
        nbr = (bb << 13) + j;
        rx = xyz[pi*2]     - xyz[nbr*2];
        ry = xyz[pi*2 + 1] - xyz[nbr*2 + 1];
    }

    float qf[8];
    {
        uint4 qv = *(const uint4*)(qkv + (size_t)pi*QKVW + lane*8);
        const __half2* qh = (const __half2*)&qv;
        #pragma unroll
        for (int i = 0; i < 4; i++) {
            float2 f = __half22float2(qh[i]);
            qf[2*i] = f.x; qf[2*i+1] = f.y;
        }
    }

    float attn[16];
    #pragma unroll
    for (int k = 0; k < 16; k++) {
        int rowk = __shfl_sync(0xffffffffu, nbr, k);
        uint4 kv = *(const uint4*)(qkv + (size_t)rowk*QKVW + CH + lane*8);
        const __half2* kh = (const __half2*)&kv;
        float pr = 0.f;
        #pragma unroll
        for (int i = 0; i < 4; i++) {
            float2 f = __half22float2(kh[i]);
            pr = fmaf(qf[2*i], f.x, pr);
            pr = fmaf(qf[2*i+1], f.y, pr);
        }
        pr += __shfl_xor_sync(0xffffffffu, pr, 4);
        pr += __shfl_xor_sync(0xffffffffu, pr, 2);
        pr += __shfl_xor_sync(0xffffffffu, pr, 1);
        attn[k] = pr * 0.125f;
    }

    float mx = -1e30f;
    #pragma unroll
    for (int k = 0; k < 16; k++) mx = fmaxf(mx, attn[k]);
    float sm = 0.f;
    #pragma unroll
    for (int k = 0; k < 16; k++) { attn[k] = __expf(attn[k] - mx); sm += attn[k]; }
    float inv = 1.f / sm;
    #pragma unroll
    for (int k = 0; k < 16; k++) attn[k] *= inv;

    float wd1x[8], wd1y[8], bd1v[8];
    #pragma unroll
    for (int j = 0; j < 8; j++) {
        int c = lane*8 + j;
        wd1x[j] = w_d1[c]; wd1y[j] = w_d1[CH + c]; bd1v[j] = b_d1[c];
    }

    float av[8], u[4][8];
    #pragma unroll
    for (int j = 0; j < 8; j++) {
        av[j] = 0.f;
        u[0][j] = u[1][j] = u[2][j] = u[3][j] = 0.f;
    }

    #pragma unroll
    for (int k = 0; k < 16; k++) {
        int   rowk = __shfl_sync(0xffffffffu, nbr, k);
        float rxk  = __shfl_sync(0xffffffffu, rx, k);
        float ryk  = __shfl_sync(0xffffffffu, ry, k);
        float a0 = __shfl_sync(0xffffffffu, attn[k], 0);
        float a1 = __shfl_sync(0xffffffffu, attn[k], 8);
        float a2 = __shfl_sync(0xffffffffu, attn[k], 16);
        float a3 = __shfl_sync(0xffffffffu, attn[k], 24);

        uint4 vv = *(const uint4*)(qkv + (size_t)rowk*QKVW + 2*CH + lane*8);
        const __half2* vh = (const __half2*)&vv;
        #pragma unroll
        for (int i = 0; i < 4; i++) {
            float2 f = __half22float2(vh[i]);
            #pragma unroll
            for (int q2 = 0; q2 < 2; q2++) {
                int j = 2*i + q2;
                float vf = q2 ? f.y : f.x;
                av[j] = fmaf(attn[k], vf, av[j]);
                float t = fmaxf(fmaf(rxk, wd1x[j], fmaf(ryk, wd1y[j], bd1v[j])), 0.f);
                u[0][j] = fmaf(a0, t, u[0][j]);
                u[1][j] = fmaf(a1, t, u[1][j]);
                u[2][j] = fmaf(a2, t, u[2][j]);
                u[3][j] = fmaf(a3, t, u[3][j]);
            }
        }
    }

    #pragma unroll
    for (int h = 0; h < 4; h++) {
        __half2 tmp[4];
        #pragma unroll
        for (int i = 0; i < 4; i++)
            tmp[i] = __floats2half2_rn(u[h][2*i], u[h][2*i+1]);
        *(uint4*)&s_u[p][h*CH + lane*8] = *(uint4*)tmp;
    }
    *(float4*)&s_av[p][lane*8]     = make_float4(av[0], av[1], av[2], av[3]);
    *(float4*)&s_av[p][lane*8 + 4] = make_float4(av[4], av[5], av[6], av[7]);
    __syncthreads();

    // block-wide pe projection: out_c += sum_j u[h(c), j] * w_d2[j, c]
    int c = tid;
    int h = c >> 6;
    __half2 acca[AP], accb[AP];
    #pragma unroll
    for (int q2 = 0; q2 < AP; q2++) {
        acca[q2] = __floats2half2_rn(0.f, 0.f);
        accb[q2] = __floats2half2_rn(0.f, 0.f);
    }
    const __half* wrow = w_d2t + (size_t)c * CH;
    #pragma unroll 4
    for (int j8 = 0; j8 < CH/8; j8++) {
        uint4 wv = *(const uint4*)(wrow + j8*8);
        const __half2* w2 = (const __half2*)&wv;
        #pragma unroll
        for (int q2 = 0; q2 < AP; q2++) {
            uint4 uv = *(const uint4*)&s_u[q2][h*CH + j8*8];
            const __half2* u2 = (const __half2*)&uv;
            acca[q2] = __hfma2(u2[0], w2[0], acca[q2]);
            accb[q2] = __hfma2(u2[1], w2[1], accb[q2]);
            acca[q2] = __hfma2(u2[2], w2[2], acca[q2]);
            accb[q2] = __hfma2(u2[3], w2[3], accb[q2]);
        }
    }
    float bd2 = b_d2[c];
    #pragma unroll
    for (int q2 = 0; q2 < AP; q2++) {
        float2 fa = __half22float2(acca[q2]);
        float2 fb = __half22float2(accb[q2]);
        float val = s_av[q2][c] + fa.x + fa.y + fb.x + fb.y + bd2;
        xattn[(size_t)(blockIdx.x*AP + q2)*CH + c] = __float2half(val);
    }
}

// -------------------- launch ----------------------------------------------
extern "C" void kernel_launch(void* const* d_in, const int* in_sizes, int n_in,
                              void* d_out, int out_size)
{
    const float* xyz      = (const float*)d_in[0];
    const float* xy_embed = (const float*)d_in[1];
    const int*   nns      = (const int*)  d_in[2];
    const float* ln1_g    = (const float*)d_in[3];
    const float* ln1_b    = (const float*)d_in[4];
    const float* w_qkv    = (const float*)d_in[5];
    const float* w_d1     = (const float*)d_in[6];
    const float* b_d1     = (const float*)d_in[7];
    const float* w_d2     = (const float*)d_in[8];
    const float* b_d2     = (const float*)d_in[9];
    const float* w_proj   = (const float*)d_in[10];
    const float* b_proj   = (const float*)d_in[11];
    const float* ln2_g    = (const float*)d_in[12];
    const float* ln2_b    = (const float*)d_in[13];
    const float* w_m1     = (const float*)d_in[14];
    const float* b_m1     = (const float*)d_in[15];
    const float* w_m2     = (const float*)d_in[16];
    const float* b_m2     = (const float*)d_in[17];
    float* out = (float*)d_out;

    __half *h, *qkvh, *xattn, *mlp1, *wqkv16, *wproj16, *wm1_16, *wm2_16, *wd2t;
    float *x;
    cudaGetSymbolAddress((void**)&h,       g_h);
    cudaGetSymbolAddress((void**)&qkvh,    g_qkvh);
    cudaGetSymbolAddress((void**)&xattn,   g_xattn);
    cudaGetSymbolAddress((void**)&x,       g_x);
    cudaGetSymbolAddress((void**)&mlp1,    g_mlp1);
    cudaGetSymbolAddress((void**)&wqkv16,  g_wqkv16);
    cudaGetSymbolAddress((void**)&wproj16, g_wproj16);
    cudaGetSymbolAddress((void**)&wm1_16,  g_wm1_16);
    cudaGetSymbolAddress((void**)&wm2_16,  g_wm2_16);
    cudaGetSymbolAddress((void**)&wd2t,    g_wd2t);

    cudaFuncSetAttribute(hgemm<0, __half>,
        cudaFuncAttributeMaxDynamicSharedMemorySize, HSMEM_BYTES);
    cudaFuncSetAttribute(hgemm<1, float>,
        cudaFuncAttributeMaxDynamicSharedMemorySize, HSMEM_BYTES);
    cudaFuncSetAttribute(hgemm<2, __half>,
        cudaFuncAttributeMaxDynamicSharedMemorySize, HSMEM_BYTES);

    // 0. weight conversions (tiny)
    f2h_kernel<<<(CH*QKVW + 255)/256, 256>>>(w_qkv, wqkv16, CH*QKVW);
    f2h_kernel<<<(CH*CH   + 255)/256, 256>>>(w_proj, wproj16, CH*CH);
    f2h_kernel<<<(CH*1024 + 255)/256, 256>>>(w_m1, wm1_16, CH*1024);
    f2h_kernel<<<(1024*CH + 255)/256, 256>>>(w_m2, wm2_16, 1024*CH);
    wd2t_kernel<<<(CH*CH + 255)/256, 256>>>(w_d2, wd2t);

    // 1. LN1 -> half
    ln_kernel<<<NPTS/8, 256>>>(xy_embed, ln1_g, ln1_b, h);
    // 2. qkv = h @ w_qkv  (32768 x 768 x 256)
    hgemm<0, __half><<<dim3(QKVW/HBN, NPTS/HBM), 256, HSMEM_BYTES>>>(
        h, wqkv16, qkvh, NPTS, QKVW, CH, nullptr, nullptr);
    // 3. KNN attention (warp/point) + fused pe projection
    attn_kernel<<<NPTS/AP, 256>>>(qkvh, nns, xyz, w_d1, b_d1, wd2t, b_d2, xattn);
    // 4. x = xy_embed + xattn @ w_proj + b_proj  (fp32 residual)
    hgemm<1, float><<<dim3(CH/HBN, NPTS/HBM), 256, HSMEM_BYTES>>>(
        xattn, wproj16, x, NPTS, CH, CH, b_proj, xy_embed);
    // 5. LN2 -> half
    ln_kernel<<<NPTS/8, 256>>>(x, ln2_g, ln2_b, h);
    // 6. mlp1 = gelu(h @ w_m1 + b_m1)  (32768 x 1024 x 256)
    hgemm<2, __half><<<dim3(1024/HBN, NPTS/HBM), 256, HSMEM_BYTES>>>(
        h, wm1_16, mlp1, NPTS, 1024, CH, b_m1, nullptr);
    // 7. out = x + mlp1 @ w_m2 + b_m2  (32768 x 256 x 1024)
    hgemm<1, float><<<dim3(CH/HBN, NPTS/HBM), 256, HSMEM_BYTES>>>(
        mlp1, wm2_16, out, NPTS, CH, 1024, b_m2, x);
}